// round 6
// baseline (speedup 1.0000x reference)
#include <cuda_runtime.h>

#define Bv 8
#define Cv 128
#define Hv 128
#define Wv 128
#define KK 9

typedef unsigned long long u64;

// Scratch (no allocations allowed in kernel_launch)
__device__ float g_pooled[Bv * Cv];
__device__ float g_kern[Bv * Cv * KK];

// ---- packed f32x2 helpers (Blackwell FFMA2 via PTX) ------------------------
__device__ __forceinline__ u64 pack2(float lo, float hi) {
    u64 r;
    asm("mov.b64 %0, {%1, %2};" : "=l"(r) : "f"(lo), "f"(hi));
    return r;
}
__device__ __forceinline__ u64 fma2(u64 a, u64 b, u64 c) {
    u64 d;
    asm("fma.rn.f32x2 %0, %1, %2, %3;" : "=l"(d) : "l"(a), "l"(b), "l"(c));
    return d;
}
__device__ __forceinline__ u64 mul2(u64 a, u64 b) {
    u64 d;
    asm("mul.rn.f32x2 %0, %1, %2;" : "=l"(d) : "l"(a), "l"(b));
    return d;
}
__device__ __forceinline__ float lo2(u64 v) {
    float a, b;
    asm("mov.b64 {%0, %1}, %2;" : "=f"(a), "=f"(b) : "l"(v));
    return a;
}
__device__ __forceinline__ float hi2(u64 v) {
    float a, b;
    asm("mov.b64 {%0, %1}, %2;" : "=f"(a), "=f"(b) : "l"(v));
    return b;
}

// ---------------------------------------------------------------------------
// Kernel 1: global average pool per (b,c) plane. 1024 blocks x 256 threads.
// Default caching: populates L2 with x for the conv pass.
// ---------------------------------------------------------------------------
__global__ void pool_kernel(const float* __restrict__ x) {
    const int plane = blockIdx.x;  // b*C + c
    const float4* xp = reinterpret_cast<const float4*>(x + (size_t)plane * Hv * Wv);

    float sum = 0.f;
#pragma unroll
    for (int i = 0; i < 16; i++) {
        float4 v = xp[threadIdx.x + i * 256];
        sum += (v.x + v.y) + (v.z + v.w);
    }

    __shared__ float sdata[8];
#pragma unroll
    for (int o = 16; o; o >>= 1) sum += __shfl_down_sync(0xffffffffu, sum, o);
    if ((threadIdx.x & 31) == 0) sdata[threadIdx.x >> 5] = sum;
    __syncthreads();
    if (threadIdx.x < 8) {
        sum = sdata[threadIdx.x];
#pragma unroll
        for (int o = 4; o; o >>= 1) sum += __shfl_down_sync(0xffu, sum, o);
        if (threadIdx.x == 0) g_pooled[plane] = sum * (1.f / (float)(Hv * Wv));
    }
}

// ---------------------------------------------------------------------------
// Kernel 2: fused MLP, 288 blocks x 128 threads. Each block recomputes h for
// its batch (w1 is 64KB, L2-resident across blocks) then its 32 kern outputs.
// All weight-row loads are coalesced float4 warp-dots.
// ---------------------------------------------------------------------------
__global__ void mlp_kernel(const float* __restrict__ w1, const float* __restrict__ b1,
                           const float* __restrict__ w2, const float* __restrict__ b2) {
    const int b = blockIdx.x / 36;
    const int grp = blockIdx.x % 36;
    const int tid = threadIdx.x;
    const int wid = tid >> 5;      // 0..3
    const int lane = tid & 31;

    __shared__ float ps[Cv];
    __shared__ float hs[Cv];

    ps[tid] = g_pooled[b * Cv + tid];
    __syncthreads();

    const float4 pv = *(const float4*)&ps[lane * 4];

    // Layer 1: 128 outputs / 4 warps = 32 per warp (redundant across blocks).
#pragma unroll 4
    for (int i = 0; i < 32; i++) {
        const int o = wid * 32 + i;
        const float4 wv = *(const float4*)(w1 + (size_t)o * Cv + lane * 4);
        float acc = wv.x * pv.x;
        acc = fmaf(wv.y, pv.y, acc);
        acc = fmaf(wv.z, pv.z, acc);
        acc = fmaf(wv.w, pv.w, acc);
#pragma unroll
        for (int s = 16; s; s >>= 1) acc += __shfl_xor_sync(0xffffffffu, acc, s);
        if (lane == 0) hs[o] = fmaxf(acc + b1[o], 0.f);
    }
    __syncthreads();

    const float4 hv = *(const float4*)&hs[lane * 4];

    // Layer 2: this block's 32 outputs (8 per warp).
#pragma unroll
    for (int i = 0; i < 8; i++) {
        const int o = grp * 32 + wid * 8 + i;   // [0, 1152)
        const float4 wv = *(const float4*)(w2 + (size_t)o * Cv + lane * 4);
        float acc = wv.x * hv.x;
        acc = fmaf(wv.y, hv.y, acc);
        acc = fmaf(wv.z, hv.z, acc);
        acc = fmaf(wv.w, hv.w, acc);
#pragma unroll
        for (int s = 16; s; s >>= 1) acc += __shfl_xor_sync(0xffffffffu, acc, s);
        if (lane == 0) g_kern[b * Cv * KK + o] = acc + b2[o];
    }
}

// ---------------------------------------------------------------------------
// Kernel 3: dynamic depthwise 3x3 conv, smem-free.
// One block per plane (1024 blocks x 256 threads = 8 warps). Each warp covers
// a full 128-col row with float4 (32 lanes x 4) and slides vertically over a
// 16-row strip. Horizontal halo via 2 shfls; vertical reuse via a rotating
// 3-row register window of packed f32x2 pairs. Streaming STG.128 output.
// ---------------------------------------------------------------------------
__global__ void conv_kernel(const float* __restrict__ x, float* __restrict__ out) {
    const int plane = blockIdx.x;
    const int wid = threadIdx.x >> 5;      // 0..7  -> 16-row strip
    const int lane = threadIdx.x & 31;     // cols 4*lane .. 4*lane+3
    const int row0 = wid * 16;

    const float* xp = x + (size_t)plane * Hv * Wv;
    float* op = out + (size_t)plane * Hv * Wv;

    u64 w2p[9];
#pragma unroll
    for (int p = 0; p < 9; p++) {
        const float w = g_kern[plane * KK + p];
        w2p[p] = pack2(w, w);
    }

    // d[0]=(c-1,c0) d[1]=(c0,c1) d[2]=(c1,c2) d[3]=(c2,c3) d[4]=(c3,c4)
#define LOADROW(d, gr)                                                        \
    {                                                                         \
        if ((gr) < 0 || (gr) >= Hv) {                                         \
            d[0] = 0; d[1] = 0; d[2] = 0; d[3] = 0; d[4] = 0;                 \
        } else {                                                              \
            float4 v = __ldg((const float4*)(xp + (gr) * Wv) + lane);         \
            float cm1 = __shfl_up_sync(0xffffffffu, v.w, 1);                  \
            float cp4 = __shfl_down_sync(0xffffffffu, v.x, 1);                \
            if (lane == 0) cm1 = 0.f;                                         \
            if (lane == 31) cp4 = 0.f;                                        \
            d[0] = pack2(cm1, v.x);                                           \
            d[1] = pack2(v.x, v.y);                                           \
            d[2] = pack2(v.y, v.z);                                           \
            d[3] = pack2(v.z, v.w);                                           \
            d[4] = pack2(v.w, cp4);                                           \
        }                                                                     \
    }

    u64 r[3][5];
    LOADROW(r[0], row0 - 1);
    LOADROW(r[1], row0);

#pragma unroll
    for (int i = 0; i < 16; i++) {
        u64* rt = r[i % 3];
        u64* rm = r[(i + 1) % 3];
        u64* rb = r[(i + 2) % 3];
        LOADROW(rb, row0 + i + 1);

        // outputs (o0,o1) = cols (4l, 4l+1)
        u64 accA = mul2(rt[0], w2p[0]);
        accA = fma2(rt[1], w2p[1], accA);
        accA = fma2(rt[2], w2p[2], accA);
        accA = fma2(rm[0], w2p[3], accA);
        accA = fma2(rm[1], w2p[4], accA);
        accA = fma2(rm[2], w2p[5], accA);
        accA = fma2(rb[0], w2p[6], accA);
        accA = fma2(rb[1], w2p[7], accA);
        accA = fma2(rb[2], w2p[8], accA);

        // outputs (o2,o3) = cols (4l+2, 4l+3)
        u64 accB = mul2(rt[2], w2p[0]);
        accB = fma2(rt[3], w2p[1], accB);
        accB = fma2(rt[4], w2p[2], accB);
        accB = fma2(rm[2], w2p[3], accB);
        accB = fma2(rm[3], w2p[4], accB);
        accB = fma2(rm[4], w2p[5], accB);
        accB = fma2(rb[2], w2p[6], accB);
        accB = fma2(rb[3], w2p[7], accB);
        accB = fma2(rb[4], w2p[8], accB);

        float4 o;
        o.x = lo2(accA); o.y = hi2(accA);
        o.z = lo2(accB); o.w = hi2(accB);
        __stcs((float4*)(op + (row0 + i) * Wv) + lane, o);
    }
#undef LOADROW
}

// ---------------------------------------------------------------------------
extern "C" void kernel_launch(void* const* d_in, const int* in_sizes, int n_in,
                              void* d_out, int out_size) {
    const float* x  = (const float*)d_in[0];
    const float* w1 = (const float*)d_in[1];
    const float* b1 = (const float*)d_in[2];
    const float* w2 = (const float*)d_in[3];
    const float* b2 = (const float*)d_in[4];
    float* out = (float*)d_out;

    pool_kernel<<<Bv * Cv, 256>>>(x);
    mlp_kernel<<<Bv * 36, 128>>>(w1, b1, w2, b2);
    conv_kernel<<<Bv * Cv, 256>>>(x, out);
}

// round 7
// speedup vs baseline: 1.0417x; 1.0417x over previous
#include <cuda_runtime.h>

#define Bv 8
#define Cv 128
#define Hv 128
#define Wv 128
#define KK 9

typedef unsigned long long u64;

// Scratch (no allocations allowed in kernel_launch)
__device__ float g_pooled[Bv * Cv];
__device__ float g_h[Bv * Cv];

// ---- packed f32x2 helpers (Blackwell FFMA2 via PTX) ------------------------
__device__ __forceinline__ u64 pack2(float lo, float hi) {
    u64 r;
    asm("mov.b64 %0, {%1, %2};" : "=l"(r) : "f"(lo), "f"(hi));
    return r;
}
__device__ __forceinline__ u64 fma2(u64 a, u64 b, u64 c) {
    u64 d;
    asm("fma.rn.f32x2 %0, %1, %2, %3;" : "=l"(d) : "l"(a), "l"(b), "l"(c));
    return d;
}
__device__ __forceinline__ u64 mul2(u64 a, u64 b) {
    u64 d;
    asm("mul.rn.f32x2 %0, %1, %2;" : "=l"(d) : "l"(a), "l"(b));
    return d;
}
__device__ __forceinline__ void unpack2(u64 v, float& a, float& b) {
    asm("mov.b64 {%0, %1}, %2;" : "=f"(a), "=f"(b) : "l"(v));
}

// ---------------------------------------------------------------------------
// Kernel 1: global average pool per (b,c) plane. 1024 blocks x 256 threads.
// Also populates L2 with x for the conv pass.
// ---------------------------------------------------------------------------
__global__ void pool_kernel(const float* __restrict__ x) {
    const int plane = blockIdx.x;  // b*C + c
    const float4* xp = reinterpret_cast<const float4*>(x + (size_t)plane * Hv * Wv);

    float sum = 0.f;
#pragma unroll
    for (int i = 0; i < 16; i++) {
        float4 v = xp[threadIdx.x + i * 256];
        sum += (v.x + v.y) + (v.z + v.w);
    }

    __shared__ float sdata[8];
#pragma unroll
    for (int o = 16; o; o >>= 1) sum += __shfl_down_sync(0xffffffffu, sum, o);
    if ((threadIdx.x & 31) == 0) sdata[threadIdx.x >> 5] = sum;
    __syncthreads();
    if (threadIdx.x < 8) {
        sum = sdata[threadIdx.x];
#pragma unroll
        for (int o = 4; o; o >>= 1) sum += __shfl_down_sync(0xffu, sum, o);
        if (threadIdx.x == 0) g_pooled[plane] = sum * (1.f / (float)(Hv * Wv));
    }
}

// ---------------------------------------------------------------------------
// Kernel 2: h = relu(pooled @ w1^T + b1). 8 blocks x 128 threads, warp-dots.
// ---------------------------------------------------------------------------
__global__ void h_kernel(const float* __restrict__ w1, const float* __restrict__ b1) {
    const int b = blockIdx.x;
    const int tid = threadIdx.x;
    const int wid = tid >> 5;
    const int lane = tid & 31;

    __shared__ float ps[Cv];
    ps[tid] = g_pooled[b * Cv + tid];
    __syncthreads();

    const float4 pv = *(const float4*)&ps[lane * 4];

#pragma unroll 4
    for (int i = 0; i < 32; i++) {
        const int o = wid * 32 + i;
        const float4 wv = *(const float4*)(w1 + (size_t)o * Cv + lane * 4);
        float acc = wv.x * pv.x;
        acc = fmaf(wv.y, pv.y, acc);
        acc = fmaf(wv.z, pv.z, acc);
        acc = fmaf(wv.w, pv.w, acc);
#pragma unroll
        for (int s = 16; s; s >>= 1) acc += __shfl_xor_sync(0xffffffffu, acc, s);
        if (lane == 0) g_h[b * Cv + o] = fmaxf(acc + b1[o], 0.f);
    }
}

// ---------------------------------------------------------------------------
// Kernel 3: fused kern-generation + dynamic depthwise 3x3 conv.
// One block per plane: 1024 blocks x 512 threads (16 warps).
//  - Warps 0..8 first compute this plane's 9 kernel taps as warp-dots
//    kern[p] = dot(h[b,:], w2[c*9+p,:]) + b2[c*9+p]   (w2 rows L2-resident)
//  - Then all 16 warps convolve an 8-row strip each, shfl halo, packed
//    f32x2 FMAs, streaming STG.128.
// ---------------------------------------------------------------------------
__global__ void __launch_bounds__(512, 3)
conv_kernel(const float* __restrict__ x,
            const float* __restrict__ w2, const float* __restrict__ b2,
            float* __restrict__ out) {
    const int plane = blockIdx.x;          // b*C + c
    const int b = plane >> 7;
    const int c = plane & 127;
    const int wid = threadIdx.x >> 5;      // 0..15
    const int lane = threadIdx.x & 31;

    __shared__ float kw[KK];

    // --- inline kern generation (warps 0..8) ---
    if (wid < KK) {
        const int o = c * KK + wid;
        const float4 hv = ((const float4*)(g_h + b * Cv))[lane];
        const float4 wv = ((const float4*)(w2 + (size_t)o * Cv))[lane];
        float acc = wv.x * hv.x;
        acc = fmaf(wv.y, hv.y, acc);
        acc = fmaf(wv.z, hv.z, acc);
        acc = fmaf(wv.w, hv.w, acc);
#pragma unroll
        for (int s = 16; s; s >>= 1) acc += __shfl_xor_sync(0xffffffffu, acc, s);
        if (lane == 0) kw[wid] = acc + b2[o];
    }
    __syncthreads();

    u64 w2p[9];
#pragma unroll
    for (int p = 0; p < 9; p++) w2p[p] = pack2(kw[p], kw[p]);

    // --- conv over this warp's 8-row strip ---
    const int row0 = wid * 8;
    const float* xp = x + (size_t)plane * Hv * Wv;
    float* op = out + (size_t)plane * Hv * Wv;

    // d[0]=(c-1,c0) d[1]=(c0,c1) d[2]=(c1,c2) d[3]=(c2,c3) d[4]=(c3,c4)
#define LOADROW(d, gr)                                                        \
    {                                                                         \
        if ((gr) < 0 || (gr) >= Hv) {                                         \
            d[0] = 0; d[1] = 0; d[2] = 0; d[3] = 0; d[4] = 0;                 \
        } else {                                                              \
            float4 v = __ldg((const float4*)(xp + (gr) * Wv) + lane);         \
            float cm1 = __shfl_up_sync(0xffffffffu, v.w, 1);                  \
            float cp4 = __shfl_down_sync(0xffffffffu, v.x, 1);                \
            if (lane == 0) cm1 = 0.f;                                         \
            if (lane == 31) cp4 = 0.f;                                        \
            d[0] = pack2(cm1, v.x);                                           \
            d[1] = pack2(v.x, v.y);                                           \
            d[2] = pack2(v.y, v.z);                                           \
            d[3] = pack2(v.z, v.w);                                           \
            d[4] = pack2(v.w, cp4);                                           \
        }                                                                     \
    }

    u64 r[3][5];
    LOADROW(r[0], row0 - 1);
    LOADROW(r[1], row0);

#pragma unroll
    for (int i = 0; i < 8; i++) {
        u64* rt = r[i % 3];
        u64* rm = r[(i + 1) % 3];
        u64* rb = r[(i + 2) % 3];
        LOADROW(rb, row0 + i + 1);

        u64 accA = mul2(rt[0], w2p[0]);
        accA = fma2(rt[1], w2p[1], accA);
        accA = fma2(rt[2], w2p[2], accA);
        accA = fma2(rm[0], w2p[3], accA);
        accA = fma2(rm[1], w2p[4], accA);
        accA = fma2(rm[2], w2p[5], accA);
        accA = fma2(rb[0], w2p[6], accA);
        accA = fma2(rb[1], w2p[7], accA);
        accA = fma2(rb[2], w2p[8], accA);

        u64 accB = mul2(rt[2], w2p[0]);
        accB = fma2(rt[3], w2p[1], accB);
        accB = fma2(rt[4], w2p[2], accB);
        accB = fma2(rm[2], w2p[3], accB);
        accB = fma2(rm[3], w2p[4], accB);
        accB = fma2(rm[4], w2p[5], accB);
        accB = fma2(rb[2], w2p[6], accB);
        accB = fma2(rb[3], w2p[7], accB);
        accB = fma2(rb[4], w2p[8], accB);

        float4 o;
        unpack2(accA, o.x, o.y);
        unpack2(accB, o.z, o.w);
        __stcs((float4*)(op + (row0 + i) * Wv) + lane, o);
    }
#undef LOADROW
}

// ---------------------------------------------------------------------------
extern "C" void kernel_launch(void* const* d_in, const int* in_sizes, int n_in,
                              void* d_out, int out_size) {
    const float* x  = (const float*)d_in[0];
    const float* w1 = (const float*)d_in[1];
    const float* b1 = (const float*)d_in[2];
    const float* w2 = (const float*)d_in[3];
    const float* b2 = (const float*)d_in[4];
    float* out = (float*)d_out;

    pool_kernel<<<Bv * Cv, 256>>>(x);
    h_kernel<<<Bv, 128>>>(w1, b1);
    conv_kernel<<<Bv * Cv, 512>>>(x, w2, b2, out);
}